// round 5
// baseline (speedup 1.0000x reference)
#include <cuda_runtime.h>
#include <cstdint>

// KANStressPredictor: elementwise over [B,T,3] f32 strain.
// Per point (s0,s1,s2):
//   c00=2s0+1, c11=2s1+1, c01=s2
//   det=c00*c11-c01^2, l=log2(det)
//   mean=0.5*(c00+c11), rad=sqrt(0.25*(c00-c11)^2 + c01^2)
//   out_k = exp2( ki0*(0.5*log2(mean -/+ rad) - l/6) )  k=0,1
//   out_2 = 0.5*ln2*l * ki1
//
// Pure streaming, zero reuse: 8 points/thread = 6x LDG.128 (front-batched,
// MLP=6) + 6x STG.128, all with streaming (.cs evict-first) cache hints.

__device__ __forceinline__ void kan_point(float s0, float s1, float s2,
                                          float ki0, float ki1,
                                          float& o0, float& o1, float& o2) {
    const float c00 = fmaf(2.0f, s0, 1.0f);
    const float c11 = fmaf(2.0f, s1, 1.0f);
    const float c01 = s2;

    const float det = fmaf(c00, c11, -c01 * c01);
    const float l   = __log2f(det);                 // log2(det)

    const float mean = 0.5f * (c00 + c11);
    const float hd   = 0.5f * (c00 - c11);
    const float rad  = sqrtf(fmaf(hd, hd, c01 * c01));

    const float lm = __log2f(mean - rad);           // log2(lambda0)
    const float lp = __log2f(mean + rad);           // log2(lambda1)

    const float half_ki0 = 0.5f * ki0;
    const float base = ki0 * (l * (-1.0f / 6.0f));  // ki0*log2(det^(-1/6))

    o0 = exp2f(fmaf(half_ki0, lm, base));
    o1 = exp2f(fmaf(half_ki0, lp, base));
    o2 = (0.5f * 0.69314718055994531f) * l * ki1;   // log(sqrt(det)) * ki1
}

__device__ __forceinline__ void kan_quad(const float4& a, const float4& b, const float4& c,
                                         float ki0, float ki1,
                                         float4& oa, float4& ob, float4& oc) {
    float o[12];
    kan_point(a.x, a.y, a.z, ki0, ki1, o[0], o[1], o[2]);
    kan_point(a.w, b.x, b.y, ki0, ki1, o[3], o[4], o[5]);
    kan_point(b.z, b.w, c.x, ki0, ki1, o[6], o[7], o[8]);
    kan_point(c.y, c.z, c.w, ki0, ki1, o[9], o[10], o[11]);
    oa = make_float4(o[0], o[1], o[2],  o[3]);
    ob = make_float4(o[4], o[5], o[6],  o[7]);
    oc = make_float4(o[8], o[9], o[10], o[11]);
}

__global__ __launch_bounds__(256)
void kan_vec8_kernel(const float4* __restrict__ in, float4* __restrict__ out,
                     const float* __restrict__ ki0p, const float* __restrict__ ki1p,
                     int n_groups) {
    const int g = blockIdx.x * blockDim.x + threadIdx.x;
    if (g >= n_groups) return;

    const float ki0 = __ldg(ki0p);
    const float ki1 = __ldg(ki1p);

    const long long base = 6LL * g;

    // 6 contiguous float4 = 8 points. Front-batch all loads (MLP=6),
    // streaming hint: this data is touched exactly once.
    float4 v0 = __ldcs(in + base + 0);
    float4 v1 = __ldcs(in + base + 1);
    float4 v2 = __ldcs(in + base + 2);
    float4 v3 = __ldcs(in + base + 3);
    float4 v4 = __ldcs(in + base + 4);
    float4 v5 = __ldcs(in + base + 5);

    float4 oa, ob, oc;
    kan_quad(v0, v1, v2, ki0, ki1, oa, ob, oc);
    __stcs(out + base + 0, oa);
    __stcs(out + base + 1, ob);
    __stcs(out + base + 2, oc);

    kan_quad(v3, v4, v5, ki0, ki1, oa, ob, oc);
    __stcs(out + base + 3, oa);
    __stcs(out + base + 4, ob);
    __stcs(out + base + 5, oc);
}

// Scalar tail for points not covered by the vec8 kernel (normally 0 launches).
__global__ void kan_tail_kernel(const float* __restrict__ in, float* __restrict__ out,
                                const float* __restrict__ ki0p, const float* __restrict__ ki1p,
                                int start_point, int n_points) {
    const int p = start_point + blockIdx.x * blockDim.x + threadIdx.x;
    if (p >= n_points) return;
    const float ki0 = __ldg(ki0p);
    const float ki1 = __ldg(ki1p);
    float o0, o1, o2;
    kan_point(in[3 * p + 0], in[3 * p + 1], in[3 * p + 2], ki0, ki1, o0, o1, o2);
    out[3 * p + 0] = o0;
    out[3 * p + 1] = o1;
    out[3 * p + 2] = o2;
}

extern "C" void kernel_launch(void* const* d_in, const int* in_sizes, int n_in,
                              void* d_out, int out_size) {
    const float* strain = (const float*)d_in[0];
    const float* ki0p   = (const float*)d_in[1];
    const float* ki1p   = (const float*)d_in[2];
    float* out          = (float*)d_out;

    const int n_floats = in_sizes[0];          // B*T*3
    const int n_points = n_floats / 3;
    const int n_groups = n_points / 8;         // 8 points per thread
    const int tail     = n_points - n_groups * 8;

    if (n_groups > 0) {
        const int threads = 256;
        const int blocks  = (n_groups + threads - 1) / threads;
        kan_vec8_kernel<<<blocks, threads>>>(
            (const float4*)strain, (float4*)out, ki0p, ki1p, n_groups);
    }
    if (tail > 0) {
        kan_tail_kernel<<<1, 256>>>(strain, out, ki0p, ki1p, n_groups * 8, n_points);
    }
}

// round 7
// speedup vs baseline: 1.2140x; 1.2140x over previous
#include <cuda_runtime.h>
#include <cstdint>

// KANStressPredictor: elementwise over [B,T,3] f32 strain.
// Per point (s0,s1,s2):
//   c00=2s0+1, c11=2s1+1, c01=s2
//   det=c00*c11-c01^2, l=log2(det)
//   mean=0.5*(c00+c11), rad=sqrt(0.25*(c00-c11)^2 + c01^2)
//   lambda0=mean-rad; lambda1=mean+rad; note lambda0*lambda1=det
//   out0 = exp2(ki0*(0.5*log2(l0) - l/6))
//   out1 = exp2(ki0*(0.5*log2(l1) - l/6)) = exp2(ki0*l/6 - t0)   [l1=det/l0]
//   out2 = 0.5*ln2*l * ki1
// MUFU budget: 2x LG2 + 2x EX2 + 1x SQRT = 5 per point (was 6).
//
// R2 skeleton (proven 30.4us): 4 points/thread, 3x LDG.128 front-batched,
// 256 threads/block, plain (non-.cs) loads/stores.

__device__ __forceinline__ void kan_point(float s0, float s1, float s2,
                                          float half_ki0, float sixth_ki0,
                                          float ki1,
                                          float& o0, float& o1, float& o2) {
    const float c00 = fmaf(2.0f, s0, 1.0f);
    const float c11 = fmaf(2.0f, s1, 1.0f);
    const float c01 = s2;

    const float det = fmaf(c00, c11, -c01 * c01);
    const float l   = __log2f(det);                 // log2(det)

    const float mean = 0.5f * (c00 + c11);
    const float hd   = 0.5f * (c00 - c11);
    const float rad  = sqrtf(fmaf(hd, hd, c01 * c01));

    const float lm = __log2f(mean - rad);           // log2(lambda0)

    const float e  = sixth_ki0 * l;                 // ki0*l/6
    const float t0 = fmaf(half_ki0, lm, -e);        // ki0*(lm/2 - l/6)
    const float t1 = e - t0;                        // ki0*(l/3 - lm/2)

    o0 = exp2f(t0);
    o1 = exp2f(t1);
    o2 = (0.5f * 0.69314718055994531f) * l * ki1;   // log(sqrt(det)) * ki1
}

__global__ __launch_bounds__(256)
void kan_vec4_kernel(const float4* __restrict__ in, float4* __restrict__ out,
                     const float* __restrict__ ki0p, const float* __restrict__ ki1p,
                     int n_groups) {
    const int g = blockIdx.x * blockDim.x + threadIdx.x;
    if (g >= n_groups) return;

    const float ki0 = __ldg(ki0p);
    const float ki1 = __ldg(ki1p);
    const float half_ki0  = 0.5f * ki0;
    const float sixth_ki0 = ki0 * (1.0f / 6.0f);

    // 3 contiguous float4 = 4 points (12 floats), front-batched loads.
    const float4 a = in[3 * g + 0];
    const float4 b = in[3 * g + 1];
    const float4 c = in[3 * g + 2];

    float o[12];
    kan_point(a.x, a.y, a.z, half_ki0, sixth_ki0, ki1, o[0], o[1],  o[2]);
    kan_point(a.w, b.x, b.y, half_ki0, sixth_ki0, ki1, o[3], o[4],  o[5]);
    kan_point(b.z, b.w, c.x, half_ki0, sixth_ki0, ki1, o[6], o[7],  o[8]);
    kan_point(c.y, c.z, c.w, half_ki0, sixth_ki0, ki1, o[9], o[10], o[11]);

    out[3 * g + 0] = make_float4(o[0], o[1], o[2],  o[3]);
    out[3 * g + 1] = make_float4(o[4], o[5], o[6],  o[7]);
    out[3 * g + 2] = make_float4(o[8], o[9], o[10], o[11]);
}

// Scalar tail (points not covered by the vec4 kernel). Normally 0 launches.
__global__ void kan_tail_kernel(const float* __restrict__ in, float* __restrict__ out,
                                const float* __restrict__ ki0p, const float* __restrict__ ki1p,
                                int start_point, int n_points) {
    const int p = start_point + blockIdx.x * blockDim.x + threadIdx.x;
    if (p >= n_points) return;
    const float ki0 = __ldg(ki0p);
    const float ki1 = __ldg(ki1p);
    float o0, o1, o2;
    kan_point(in[3 * p + 0], in[3 * p + 1], in[3 * p + 2],
              0.5f * ki0, ki0 * (1.0f / 6.0f), ki1, o0, o1, o2);
    out[3 * p + 0] = o0;
    out[3 * p + 1] = o1;
    out[3 * p + 2] = o2;
}

extern "C" void kernel_launch(void* const* d_in, const int* in_sizes, int n_in,
                              void* d_out, int out_size) {
    const float* strain = (const float*)d_in[0];
    const float* ki0p   = (const float*)d_in[1];
    const float* ki1p   = (const float*)d_in[2];
    float* out          = (float*)d_out;

    const int n_floats = in_sizes[0];          // B*T*3
    const int n_points = n_floats / 3;
    const int n_groups = n_points / 4;         // 4 points per thread
    const int tail     = n_points - n_groups * 4;

    if (n_groups > 0) {
        const int threads = 256;
        const int blocks  = (n_groups + threads - 1) / threads;
        kan_vec4_kernel<<<blocks, threads>>>(
            (const float4*)strain, (float4*)out, ki0p, ki1p, n_groups);
    }
    if (tail > 0) {
        kan_tail_kernel<<<1, 256>>>(strain, out, ki0p, ki1p, n_groups * 4, n_points);
    }
}